// round 1
// baseline (speedup 1.0000x reference)
#include <cuda_runtime.h>
#include <math.h>

// Problem constants (match reference setup_inputs)
#define D      2048
#define K      8
#define P      256
#define NROWS  4096
#define HALF   2048
#define MARGIN 1.0f

#define THREADS 512
#define GROUP   16                 // rows per identity (2*K)
#define D4      (D / 4)            // row length in float4 = 512
#define SMEM_BYTES (GROUP * D * sizeof(float))   // 128 KB

__global__ __launch_bounds__(THREADS, 1)
void wloss_kernel(const float* __restrict__ x, float* __restrict__ out)
{
    extern __shared__ float sm[];                 // 16 rows x 2048 floats
    float4* sm4 = reinterpret_cast<float4*>(sm);
    __shared__ float inv_norm[GROUP];
    __shared__ float gram[GROUP][GROUP];

    const int p    = blockIdx.x;                  // identity
    const int tid  = threadIdx.x;
    const int w    = tid >> 5;                    // warp 0..15
    const int lane = tid & 31;

    // ---- init gram to 0 ----
    if (tid < GROUP * GROUP)
        gram[tid >> 4][tid & 15] = 0.0f;

    // ---- stage 16 member rows into smem (float4) ----
    // rows 0..7  -> global rows p*8 + r        (first half)
    // rows 8..15 -> global rows 2048 + p*8 + r (second half)
    const float4* x4 = reinterpret_cast<const float4*>(x);
    #pragma unroll
    for (int i = tid; i < GROUP * D4; i += THREADS) {
        int r = i >> 9;            // /512
        int c = i & (D4 - 1);
        int g = (r < K) ? (p * K + r) : (HALF + p * K + (r - K));
        sm4[i] = x4[(size_t)g * D4 + c];
    }
    __syncthreads();

    // ---- per-row inverse norms: warp w handles row w ----
    {
        const float4* row = sm4 + w * D4;
        float s = 0.0f;
        #pragma unroll
        for (int i = lane; i < D4; i += 32) {
            float4 v = row[i];
            s += v.x * v.x + v.y * v.y + v.z * v.z + v.w * v.w;
        }
        #pragma unroll
        for (int o = 16; o; o >>= 1)
            s += __shfl_xor_sync(0xffffffffu, s, o);
        if (lane == 0)
            inv_norm[w] = 1.0f / (sqrtf(s) + 1e-10f);
    }
    __syncthreads();

    // ---- Gram: warp (rg, dc): rows [4rg,4rg+4) x all 16 cols over D-chunk dc ----
    {
        const int rg = w & 3;        // row group
        const int dc = w >> 2;       // D chunk (of 4)
        float acc[64];
        #pragma unroll
        for (int i = 0; i < 64; i++) acc[i] = 0.0f;

        const int cbase = dc * (D4 / 4);   // 128 float4 per chunk
        #pragma unroll
        for (int it = 0; it < 4; it++) {
            int off = cbase + it * 32 + lane;       // float4 index within row
            float4 a[4];
            #pragma unroll
            for (int r = 0; r < 4; r++)
                a[r] = sm4[(4 * rg + r) * D4 + off];
            #pragma unroll
            for (int b = 0; b < GROUP; b++) {
                float4 bv = sm4[b * D4 + off];
                #pragma unroll
                for (int r = 0; r < 4; r++) {
                    acc[r * 16 + b] += a[r].x * bv.x + a[r].y * bv.y
                                     + a[r].z * bv.z + a[r].w * bv.w;
                }
            }
        }

        // merge-exchange warp reduction: 64 accs -> 2 per lane
        #pragma unroll
        for (int s = 0; s < 5; s++) {
            const int half = 32 >> s;
            const bool up = (lane >> s) & 1;
            #pragma unroll
            for (int i = 0; i < half; i++) {
                float give = up ? acc[i] : acc[i + half];
                float keep = up ? acc[i + half] : acc[i];
                acc[i] = keep + __shfl_xor_sync(0xffffffffu, give, 1 << s);
            }
        }
        // lane holds reduced sums for original indices j = 2*brev5(lane) + {0,1}
        int rb = (int)(__brev((unsigned)lane) >> 27);
        int j0 = 2 * rb;
        int row0 = 4 * rg + (j0 >> 4);
        atomicAdd(&gram[row0][j0 & 15], acc[0]);
        int j1 = j0 + 1;
        int row1 = 4 * rg + (j1 >> 4);
        atomicAdd(&gram[row1][j1 & 15], acc[1]);
    }
    __syncthreads();

    // ---- per-row mins + loss; threads 0..15 handle one row each ----
    float li = 0.0f;
    if (tid < GROUP) {
        float inA = inv_norm[tid];
        float minf = INFINITY, mins = INFINITY;
        #pragma unroll
        for (int b = 0; b < K; b++) {
            float cv = gram[tid][b] * inA * inv_norm[b];
            minf = fminf(minf, cv);
        }
        #pragma unroll
        for (int b = K; b < GROUP; b++) {
            float cv = gram[tid][b] * inA * inv_norm[b];
            mins = fminf(mins, cv);
        }
        li = fmaxf(MARGIN - minf, 0.0f) + fmaxf(MARGIN - mins, 0.0f);
    }
    if (w == 0) {
        #pragma unroll
        for (int o = 16; o; o >>= 1)
            li += __shfl_xor_sync(0xffffffffu, li, o);
        if (lane == 0)
            atomicAdd(out, li);
    }
}

extern "C" void kernel_launch(void* const* d_in, const int* in_sizes, int n_in,
                              void* d_out, int out_size)
{
    const float* x = (const float*)d_in[0];
    float* out = (float*)d_out;

    // out is poisoned; zero the scalar accumulator.
    cudaMemsetAsync(out, 0, sizeof(float), 0);

    static bool attr_set = false;
    if (!attr_set) {
        cudaFuncSetAttribute(wloss_kernel,
                             cudaFuncAttributeMaxDynamicSharedMemorySize,
                             SMEM_BYTES);
        attr_set = true;
    }

    wloss_kernel<<<P, THREADS, SMEM_BYTES>>>(x, out);
}

// round 2
// speedup vs baseline: 1.1420x; 1.1420x over previous
#include <cuda_runtime.h>
#include <math.h>

// Problem constants (match reference setup_inputs)
#define D        2048
#define K        8
#define P        256
#define HALF     2048
#define MARGIN   1.0f

#define THREADS  256
#define GROUP    16                  // rows per identity (2*K)
#define D4       (D / 4)             // 512 float4 per row
#define CHUNK_F4 256                 // float4 per row per chunk (1024 floats)
#define NCHUNK   2
#define SMEM_BYTES (GROUP * CHUNK_F4 * 16)   // 16 rows * 256 f4 * 16B = 64 KB

// Upper-triangle-of-quads work split: row-quad rg computes cols >= 4*rg.
// 40 (4row x 1col) units total, split into 4 groups of 10; 2 warps per group
// (each covering one half of the chunk's 256 float4 columns):
//   G0: rows 0-3   x cols 0..9
//   G1: rows 0-3   x cols 10..15  +  rows 12-15 x cols 12..15
//   G2: rows 4-7   x cols 4..13
//   G3: rows 4-7   x cols 14..15  +  rows 8-11  x cols 8..15
__global__ __launch_bounds__(THREADS, 2)
void wloss_kernel(const float* __restrict__ x, float* __restrict__ out)
{
    extern __shared__ float4 sm4[];          // [16][CHUNK_F4]
    __shared__ float gram[GROUP][GROUP];

    const int p       = blockIdx.x;
    const int tid     = threadIdx.x;
    const int w       = tid >> 5;            // warp 0..7
    const int lane    = tid & 31;
    const int grp     = w >> 1;              // work group 0..3
    const int halfsel = w & 1;               // which half of the chunk

    gram[tid >> 4][tid & 15] = 0.0f;

    float acc[64];
    #pragma unroll
    for (int i = 0; i < 64; i++) acc[i] = 0.0f;

    const float4* x4 = reinterpret_cast<const float4*>(x);

    for (int ch = 0; ch < NCHUNK; ch++) {
        // ---- stage chunk: 16 rows x 256 float4 (coalesced) ----
        #pragma unroll
        for (int t = 0; t < GROUP; t++) {
            int g = (t < K) ? (p * K + t) : (HALF + p * K + (t - K));
            sm4[t * CHUNK_F4 + tid] = x4[(size_t)g * D4 + ch * CHUNK_F4 + tid];
        }
        __syncthreads();

        // ---- compute partial Gram for this chunk ----
        #pragma unroll
        for (int it = 0; it < 4; it++) {
            const int pos = halfsel * 128 + it * 32 + lane;
            if (grp == 0) {
                float4 a[4];
                #pragma unroll
                for (int r = 0; r < 4; r++) a[r] = sm4[r * CHUNK_F4 + pos];
                #pragma unroll
                for (int ci = 0; ci < 10; ci++) {
                    float4 b = sm4[ci * CHUNK_F4 + pos];
                    #pragma unroll
                    for (int r = 0; r < 4; r++)
                        acc[ci * 4 + r] += a[r].x * b.x + a[r].y * b.y
                                         + a[r].z * b.z + a[r].w * b.w;
                }
            } else if (grp == 1) {
                {   // rows 0-3 x cols 10..15  -> acc[0..23]
                    float4 a[4];
                    #pragma unroll
                    for (int r = 0; r < 4; r++) a[r] = sm4[r * CHUNK_F4 + pos];
                    #pragma unroll
                    for (int ci = 0; ci < 6; ci++) {
                        float4 b = sm4[(10 + ci) * CHUNK_F4 + pos];
                        #pragma unroll
                        for (int r = 0; r < 4; r++)
                            acc[ci * 4 + r] += a[r].x * b.x + a[r].y * b.y
                                             + a[r].z * b.z + a[r].w * b.w;
                    }
                }
                {   // rows 12-15 x cols 12..15 -> acc[24..39]
                    float4 a[4];
                    #pragma unroll
                    for (int r = 0; r < 4; r++) a[r] = sm4[(12 + r) * CHUNK_F4 + pos];
                    #pragma unroll
                    for (int ci = 0; ci < 4; ci++) {
                        float4 b = sm4[(12 + ci) * CHUNK_F4 + pos];
                        #pragma unroll
                        for (int r = 0; r < 4; r++)
                            acc[24 + ci * 4 + r] += a[r].x * b.x + a[r].y * b.y
                                                  + a[r].z * b.z + a[r].w * b.w;
                    }
                }
            } else if (grp == 2) {
                // rows 4-7 x cols 4..13 -> acc[0..39]
                float4 a[4];
                #pragma unroll
                for (int r = 0; r < 4; r++) a[r] = sm4[(4 + r) * CHUNK_F4 + pos];
                #pragma unroll
                for (int ci = 0; ci < 10; ci++) {
                    float4 b = sm4[(4 + ci) * CHUNK_F4 + pos];
                    #pragma unroll
                    for (int r = 0; r < 4; r++)
                        acc[ci * 4 + r] += a[r].x * b.x + a[r].y * b.y
                                         + a[r].z * b.z + a[r].w * b.w;
                }
            } else {
                {   // rows 4-7 x cols 14..15 -> acc[0..7]
                    float4 a[4];
                    #pragma unroll
                    for (int r = 0; r < 4; r++) a[r] = sm4[(4 + r) * CHUNK_F4 + pos];
                    #pragma unroll
                    for (int ci = 0; ci < 2; ci++) {
                        float4 b = sm4[(14 + ci) * CHUNK_F4 + pos];
                        #pragma unroll
                        for (int r = 0; r < 4; r++)
                            acc[ci * 4 + r] += a[r].x * b.x + a[r].y * b.y
                                             + a[r].z * b.z + a[r].w * b.w;
                    }
                }
                {   // rows 8-11 x cols 8..15 -> acc[8..39]
                    float4 a[4];
                    #pragma unroll
                    for (int r = 0; r < 4; r++) a[r] = sm4[(8 + r) * CHUNK_F4 + pos];
                    #pragma unroll
                    for (int ci = 0; ci < 8; ci++) {
                        float4 b = sm4[(8 + ci) * CHUNK_F4 + pos];
                        #pragma unroll
                        for (int r = 0; r < 4; r++)
                            acc[8 + ci * 4 + r] += a[r].x * b.x + a[r].y * b.y
                                                 + a[r].z * b.z + a[r].w * b.w;
                    }
                }
            }
        }
        __syncthreads();   // before next chunk overwrites smem
    }

    // ---- merge-exchange warp reduction: 64 accs -> 2 per lane ----
    #pragma unroll
    for (int s = 0; s < 5; s++) {
        const int half = 32 >> s;
        const bool up = (lane >> s) & 1;
        #pragma unroll
        for (int i = 0; i < half; i++) {
            float give = up ? acc[i] : acc[i + half];
            float keep = up ? acc[i + half] : acc[i];
            acc[i] = keep + __shfl_xor_sync(0xffffffffu, give, 1 << s);
        }
    }
    // lane holds reduced sums for original indices u = 2*brev5(lane) + {0,1}
    {
        int rb = (int)(__brev((unsigned)lane) >> 27);
        #pragma unroll
        for (int q = 0; q < 2; q++) {
            int u = 2 * rb + q;
            if (u < 40) {
                int row, col;
                if (grp == 0)      { col = u >> 2;            row = u & 3; }
                else if (grp == 1) {
                    if (u < 24)    { col = 10 + (u >> 2);     row = u & 3; }
                    else { int v = u - 24; col = 12 + (v >> 2); row = 12 + (v & 3); }
                } else if (grp == 2) { col = 4 + (u >> 2);    row = 4 + (u & 3); }
                else {
                    if (u < 8)     { col = 14 + (u >> 2);     row = 4 + (u & 3); }
                    else { int v = u - 8;  col = 8 + (v >> 2);  row = 8 + (v & 3); }
                }
                atomicAdd(&gram[row][col], acc[q]);
            }
        }
    }
    __syncthreads();

    // ---- mins + loss (warp 0; diag of gram == squared norms) ----
    if (w == 0) {
        const int r = lane & 15;
        float inv = 1.0f / (sqrtf(gram[r][r]) + 1e-10f);
        float minf = INFINITY, mins = INFINITY;
        #pragma unroll
        for (int c = 0; c < GROUP; c++) {
            float invc = __shfl_sync(0xffffffffu, inv, c);
            float raw  = (c >= 4 * (r >> 2)) ? gram[r][c] : gram[c][r];
            float v = raw * inv * invc;
            if (c < K) minf = fminf(minf, v);
            else       mins = fminf(mins, v);
        }
        float li = fmaxf(MARGIN - minf, 0.0f) + fmaxf(MARGIN - mins, 0.0f);
        if (lane >= 16) li = 0.0f;
        #pragma unroll
        for (int o = 16; o; o >>= 1)
            li += __shfl_xor_sync(0xffffffffu, li, o);
        if (lane == 0)
            atomicAdd(out, li);
    }
}

extern "C" void kernel_launch(void* const* d_in, const int* in_sizes, int n_in,
                              void* d_out, int out_size)
{
    const float* x = (const float*)d_in[0];
    float* out = (float*)d_out;

    cudaMemsetAsync(out, 0, sizeof(float), 0);

    static bool attr_set = false;
    if (!attr_set) {
        cudaFuncSetAttribute(wloss_kernel,
                             cudaFuncAttributeMaxDynamicSharedMemorySize,
                             SMEM_BYTES);
        attr_set = true;
    }

    wloss_kernel<<<P, THREADS, SMEM_BYTES>>>(x, out);
}

// round 3
// speedup vs baseline: 1.2867x; 1.1267x over previous
#include <cuda_runtime.h>
#include <math.h>
#include <stdint.h>

// Problem constants (match reference setup_inputs)
#define D        2048
#define K        8
#define P        256
#define HALF     2048
#define MARGIN   1.0f

#define THREADS  256
#define GROUP    16                 // rows per identity (2*K)
#define D4       (D / 4)            // 512 float4 per row
#define CHUNK_F4 128                // float4 per row per chunk (512 floats)
#define NCHUNK   4
#define BUF_F4   (GROUP * CHUNK_F4) // 2048 float4 = 32 KB per buffer
#define SMEM_BYTES (2 * BUF_F4 * 16)  // 64 KB (double buffered)

// packed f32x2 FMA: acc(2xf32) += a(2xf32) * b(2xf32)
#define FMA2(acc, a, b) \
    asm("fma.rn.f32x2 %0, %1, %2, %0;" : "+l"(acc) : "l"(a), "l"(b))

__device__ __forceinline__ void cp_async16(uint32_t dst_smem, const void* src) {
    asm volatile("cp.async.cg.shared.global [%0], [%1], 16;"
                 :: "r"(dst_smem), "l"(src));
}
#define CP_COMMIT() asm volatile("cp.async.commit_group;" ::: "memory")
#define CP_WAIT1()  asm volatile("cp.async.wait_group 1;" ::: "memory")

// One (4 rows x NC cols) FFMA2 block at float4-position pos.
template <int NC>
__device__ __forceinline__ void block_fma(const float4* __restrict__ smbuf,
                                          int pos, int rowBase, int colBase,
                                          unsigned long long* __restrict__ acc2,
                                          int accBase)
{
    ulonglong2 A[4];
    #pragma unroll
    for (int r = 0; r < 4; r++)
        A[r] = *reinterpret_cast<const ulonglong2*>(
                   &smbuf[(rowBase + r) * CHUNK_F4 + pos]);
    #pragma unroll
    for (int ci = 0; ci < NC; ci++) {
        ulonglong2 B = *reinterpret_cast<const ulonglong2*>(
                           &smbuf[(colBase + ci) * CHUNK_F4 + pos]);
        #pragma unroll
        for (int r = 0; r < 4; r++) {
            FMA2(acc2[accBase + ci * 4 + r], A[r].x, B.x);
            FMA2(acc2[accBase + ci * 4 + r], A[r].y, B.y);
        }
    }
}

// Work split (upper triangle of 4x4 quads; 40 row4xcol1 units), 2 warps/group:
//   G0: rows 0-3  x cols 0..9
//   G1: rows 0-3  x cols 10..15  +  rows 12-15 x cols 12..15
//   G2: rows 4-7  x cols 4..13
//   G3: rows 4-7  x cols 14..15  +  rows 8-11  x cols 8..15
__global__ __launch_bounds__(THREADS, 2)
void wloss_kernel(const float* __restrict__ x, float* __restrict__ out)
{
    extern __shared__ float4 smbuf[];        // [2][16][CHUNK_F4]
    __shared__ float gram[GROUP][GROUP];

    const int p       = blockIdx.x;
    const int tid     = threadIdx.x;
    const int w       = tid >> 5;            // warp 0..7
    const int lane    = tid & 31;
    const int grp     = w >> 1;
    const int halfsel = w & 1;

    gram[tid >> 4][tid & 15] = 0.0f;

    unsigned long long acc2[40];
    #pragma unroll
    for (int i = 0; i < 40; i++) acc2[i] = 0ull;

    const float4* x4 = reinterpret_cast<const float4*>(x);
    const uint32_t smem_base =
        (uint32_t)__cvta_generic_to_shared(&smbuf[0]);

    // ---- staging: 8 cp.async of 16B per thread per chunk ----
    #define STAGE(ch, b)                                                     \
        do {                                                                 \
            _Pragma("unroll")                                                \
            for (int t = 0; t < 8; t++) {                                    \
                int i   = t * 256 + tid;                                     \
                int row = i >> 7;                                            \
                int c   = i & (CHUNK_F4 - 1);                                \
                int g   = (row < K) ? (p * K + row)                          \
                                    : (HALF + p * K + (row - K));            \
                cp_async16(smem_base + (uint32_t)((b) * BUF_F4 +             \
                                                  row * CHUNK_F4 + c) * 16u, \
                           x4 + (size_t)g * D4 + (ch) * CHUNK_F4 + c);       \
            }                                                                \
        } while (0)

    STAGE(0, 0); CP_COMMIT();
    STAGE(1, 1); CP_COMMIT();

    for (int ch = 0; ch < NCHUNK; ch++) {
        CP_WAIT1();
        __syncthreads();             // buffer (ch&1) fully visible to all

        const float4* buf = smbuf + (ch & 1) * BUF_F4;
        #pragma unroll
        for (int it = 0; it < 2; it++) {
            const int pos = halfsel * 64 + it * 32 + lane;
            if (grp == 0) {
                block_fma<10>(buf, pos, 0, 0, acc2, 0);
            } else if (grp == 1) {
                block_fma<6>(buf, pos, 0, 10, acc2, 0);
                block_fma<4>(buf, pos, 12, 12, acc2, 24);
            } else if (grp == 2) {
                block_fma<10>(buf, pos, 4, 4, acc2, 0);
            } else {
                block_fma<2>(buf, pos, 4, 14, acc2, 0);
                block_fma<8>(buf, pos, 8, 8, acc2, 8);
            }
        }
        __syncthreads();             // all warps done with buffer (ch&1)

        if (ch + 2 < NCHUNK) STAGE(ch + 2, ch & 1);
        CP_COMMIT();                 // keep one group per iteration
    }
    #undef STAGE

    // ---- unpack packed accumulators ----
    float acc[64];
    #pragma unroll
    for (int i = 0; i < 64; i++) acc[i] = 0.0f;
    #pragma unroll
    for (int i = 0; i < 40; i++) {
        float2 f = *reinterpret_cast<float2*>(&acc2[i]);
        acc[i] = f.x + f.y;
    }

    // ---- merge-exchange warp reduction: 64 accs -> 2 per lane ----
    #pragma unroll
    for (int s = 0; s < 5; s++) {
        const int half = 32 >> s;
        const bool up = (lane >> s) & 1;
        #pragma unroll
        for (int i = 0; i < half; i++) {
            float give = up ? acc[i] : acc[i + half];
            float keep = up ? acc[i + half] : acc[i];
            acc[i] = keep + __shfl_xor_sync(0xffffffffu, give, 1 << s);
        }
    }
    // lane holds reduced sums for original indices u = 2*brev5(lane) + {0,1}
    {
        int rb = (int)(__brev((unsigned)lane) >> 27);
        #pragma unroll
        for (int q = 0; q < 2; q++) {
            int u = 2 * rb + q;
            if (u < 40) {
                int row, col;
                if (grp == 0)      { col = u >> 2;            row = u & 3; }
                else if (grp == 1) {
                    if (u < 24)    { col = 10 + (u >> 2);     row = u & 3; }
                    else { int v = u - 24; col = 12 + (v >> 2); row = 12 + (v & 3); }
                } else if (grp == 2) { col = 4 + (u >> 2);    row = 4 + (u & 3); }
                else {
                    if (u < 8)     { col = 14 + (u >> 2);     row = 4 + (u & 3); }
                    else { int v = u - 8;  col = 8 + (v >> 2);  row = 8 + (v & 3); }
                }
                atomicAdd(&gram[row][col], acc[q]);
            }
        }
    }
    __syncthreads();

    // ---- mins + loss (warp 0; diag of gram == squared norms) ----
    if (w == 0) {
        const int r = lane & 15;
        float inv = 1.0f / (sqrtf(gram[r][r]) + 1e-10f);
        float minf = INFINITY, mins = INFINITY;
        #pragma unroll
        for (int c = 0; c < GROUP; c++) {
            float invc = __shfl_sync(0xffffffffu, inv, c);
            float raw  = (c >= 4 * (r >> 2)) ? gram[r][c] : gram[c][r];
            float v = raw * inv * invc;
            if (c < K) minf = fminf(minf, v);
            else       mins = fminf(mins, v);
        }
        float li = fmaxf(MARGIN - minf, 0.0f) + fmaxf(MARGIN - mins, 0.0f);
        if (lane >= 16) li = 0.0f;
        #pragma unroll
        for (int o = 16; o; o >>= 1)
            li += __shfl_xor_sync(0xffffffffu, li, o);
        if (lane == 0)
            atomicAdd(out, li);
    }
}

extern "C" void kernel_launch(void* const* d_in, const int* in_sizes, int n_in,
                              void* d_out, int out_size)
{
    const float* x = (const float*)d_in[0];
    float* out = (float*)d_out;

    cudaMemsetAsync(out, 0, sizeof(float), 0);

    static bool attr_set = false;
    if (!attr_set) {
        cudaFuncSetAttribute(wloss_kernel,
                             cudaFuncAttributeMaxDynamicSharedMemorySize,
                             SMEM_BYTES);
        attr_set = true;
    }

    wloss_kernel<<<P, THREADS, SMEM_BYTES>>>(x, out);
}

// round 5
// speedup vs baseline: 1.7981x; 1.3975x over previous
#include <cuda_runtime.h>
#include <math.h>
#include <stdint.h>

// Problem constants (match reference setup_inputs)
#define DIMF     2048
#define KIDS     8
#define P        256
#define HALF     2048
#define MARGIN   1.0f

#define THREADS  256
#define GROUP    16                    // rows per identity (2*K)
#define CHUNK    512                   // K floats per chunk
#define NCHUNK   (DIMF / CHUNK)        // 4
#define STRIDE_F 516                   // padded smem row stride (floats) -> conflict-free frags
#define ROW_BYTES    (CHUNK * 4)       // 2048 B copied per row per chunk
#define STRIDE_BYTES (STRIDE_F * 4)    // 2064 (16B multiple)
#define BUF_FLOATS   (GROUP * STRIDE_F)
#define BUF_BYTES    (GROUP * STRIDE_BYTES)   // 33024
#define SMEM_BYTES   (2 * BUF_BYTES)          // 66048 (double buffer)

// D(16x8) += A(16x8) * B(8x8), tf32. Gram trick: B fragments are A fragments.
#define MMA_TF32(d, a0, a1, a2, a3, b0, b1)                                \
    asm volatile(                                                          \
        "mma.sync.aligned.m16n8k8.row.col.f32.tf32.tf32.f32 "              \
        "{%0,%1,%2,%3}, {%4,%5,%6,%7}, {%8,%9}, {%0,%1,%2,%3};"            \
        : "+f"(d[0]), "+f"(d[1]), "+f"(d[2]), "+f"(d[3])                   \
        : "r"(a0), "r"(a1), "r"(a2), "r"(a3), "r"(b0), "r"(b1))

__device__ __forceinline__ uint32_t smem_u32(const void* p) {
    return (uint32_t)__cvta_generic_to_shared(p);
}
__device__ __forceinline__ void mbar_wait(uint32_t mbar, uint32_t parity) {
    asm volatile(
        "{\n\t.reg .pred P1;\n\t"
        "LAB_WAIT_%=:\n\t"
        "mbarrier.try_wait.parity.acquire.cta.shared::cta.b64 P1, [%0], %1, 0x989680;\n\t"
        "@P1 bra.uni LAB_DONE_%=;\n\t"
        "bra.uni LAB_WAIT_%=;\n\t"
        "LAB_DONE_%=:\n\t}"
        :: "r"(mbar), "r"(parity) : "memory");
}

__global__ __launch_bounds__(THREADS, 2)
void wloss_kernel(const float* __restrict__ x, float* __restrict__ out)
{
    extern __shared__ float smf[];               // [2][16][STRIDE_F]
    __shared__ float    gram[GROUP][GROUP];
    __shared__ uint64_t s_mbar[2];

    const int p    = blockIdx.x;                 // identity
    const int tid  = threadIdx.x;
    const int w    = tid >> 5;                   // warp 0..7 (K split)
    const int lane = tid & 31;

    const uint32_t smbase = smem_u32(smf);
    const uint32_t mb0 = smem_u32(&s_mbar[0]);
    const uint32_t mb1 = smem_u32(&s_mbar[1]);

    if (tid < GROUP * GROUP)
        gram[tid >> 4][tid & 15] = 0.0f;
    if (tid == 0) {
        asm volatile("mbarrier.init.shared.b64 [%0], 1;" :: "r"(mb0) : "memory");
        asm volatile("mbarrier.init.shared.b64 [%0], 1;" :: "r"(mb1) : "memory");
    }
    __syncthreads();

    // ---- bulk-async staging: 16 rows x 2KB per chunk, mbarrier-tracked ----
    auto stage = [&](int ch, int b) {
        uint32_t mb = b ? mb1 : mb0;
        asm volatile("mbarrier.arrive.expect_tx.shared.b64 _, [%0], %1;"
                     :: "r"(mb), "r"((uint32_t)(GROUP * ROW_BYTES)) : "memory");
        #pragma unroll
        for (int r = 0; r < GROUP; r++) {
            int grow = (r < KIDS) ? (p * KIDS + r)
                                  : (HALF + p * KIDS + (r - KIDS));
            const float* src = x + (size_t)grow * DIMF + ch * CHUNK;
            uint32_t dst = smbase + (uint32_t)(b * BUF_BYTES + r * STRIDE_BYTES);
            asm volatile(
                "cp.async.bulk.shared::cluster.global.mbarrier::complete_tx::bytes "
                "[%0], [%1], %2, [%3];"
                :: "r"(dst), "l"(src), "r"((uint32_t)ROW_BYTES), "r"(mb)
                : "memory");
        }
    };

    if (tid == 0) { stage(0, 0); stage(1, 1); }

    // ---- main loop: warp w handles K-slab [w*64, w*64+64) of each chunk ----
    float d1[4] = {0.f, 0.f, 0.f, 0.f};          // cols 0..7
    float d2[4] = {0.f, 0.f, 0.f, 0.f};          // cols 8..15
    const int fr = lane >> 2;                    // fragment row 0..7
    const int ft = lane & 3;                     // fragment k 0..3

    for (int ch = 0; ch < NCHUNK; ch++) {
        const int b = ch & 1;
        mbar_wait(b ? mb1 : mb0, (uint32_t)((ch >> 1) & 1));

        const float* buf = smf + b * BUF_FLOATS;
        const float* b0p = buf + fr * STRIDE_F + w * 64 + ft;
        const float* b1p = b0p + 8 * STRIDE_F;
        #pragma unroll
        for (int s = 0; s < 8; s++) {
            uint32_t a0 = __float_as_uint(b0p[s * 8]);
            uint32_t a2 = __float_as_uint(b0p[s * 8 + 4]);
            uint32_t a1 = __float_as_uint(b1p[s * 8]);
            uint32_t a3 = __float_as_uint(b1p[s * 8 + 4]);
            MMA_TF32(d1, a0, a1, a2, a3, a0, a2);   // B = rows 0..7
            MMA_TF32(d2, a0, a1, a2, a3, a1, a3);   // B = rows 8..15
        }
        __syncthreads();                          // all warps done with buffer b
        if (ch + 2 < NCHUNK && tid == 0) stage(ch + 2, b);
    }

    // ---- reduce 8 warps' partial grams into smem ----
    {
        const int rr = lane >> 2;
        const int cc = 2 * (lane & 3);
        atomicAdd(&gram[rr][cc],         d1[0]);
        atomicAdd(&gram[rr][cc + 1],     d1[1]);
        atomicAdd(&gram[rr + 8][cc],     d1[2]);
        atomicAdd(&gram[rr + 8][cc + 1], d1[3]);
        atomicAdd(&gram[rr][8 + cc],         d2[0]);
        atomicAdd(&gram[rr][8 + cc + 1],     d2[1]);
        atomicAdd(&gram[rr + 8][8 + cc],     d2[2]);
        atomicAdd(&gram[rr + 8][8 + cc + 1], d2[3]);
    }
    __syncthreads();

    // ---- mins + loss (warp 0; diag of gram == squared norms) ----
    if (w == 0) {
        const int r = lane & 15;
        float inv = 1.0f / (sqrtf(gram[r][r]) + 1e-10f);
        float minf = INFINITY, mins = INFINITY;
        #pragma unroll
        for (int c = 0; c < GROUP; c++) {
            float invc = __shfl_sync(0xffffffffu, inv, c);
            float v = gram[r][c] * inv * invc;
            if (c < KIDS) minf = fminf(minf, v);
            else          mins = fminf(mins, v);
        }
        float li = fmaxf(MARGIN - minf, 0.0f) + fmaxf(MARGIN - mins, 0.0f);
        if (lane >= 16) li = 0.0f;
        #pragma unroll
        for (int o = 16; o; o >>= 1)
            li += __shfl_xor_sync(0xffffffffu, li, o);
        if (lane == 0)
            atomicAdd(out, li);
    }
}

extern "C" void kernel_launch(void* const* d_in, const int* in_sizes, int n_in,
                              void* d_out, int out_size)
{
    const float* x = (const float*)d_in[0];
    float* out = (float*)d_out;

    cudaMemsetAsync(out, 0, sizeof(float), 0);

    static bool attr_set = false;
    if (!attr_set) {
        cudaFuncSetAttribute(wloss_kernel,
                             cudaFuncAttributeMaxDynamicSharedMemorySize,
                             SMEM_BYTES);
        attr_set = true;
    }

    wloss_kernel<<<P, THREADS, SMEM_BYTES>>>(x, out);
}